// round 9
// baseline (speedup 1.0000x reference)
#include <cuda_runtime.h>

// x[64, 64, 64, 128] fp32.
//   out1 = FWHT along axis 1 (i), element stride 8192
//   out2 = FWHT along axis 2 (j) of out1, element stride 128
// d_out = [out1 | out2].
//
// Single pipelined kernel, per-BATCH dependency:
//   block b (2048 total): batch = b/32, sub = b%32.
//   Step 1: pass-1 unit (FWHT_i of 256 columns of this batch), count up.
//   Step 2: spin until all 32 sibling blocks of this batch finished pass 1
//           (siblings are co-resident -> wait is just intra-batch skew),
//           then pass-2 unit (FWHT_j) reading out1[batch] from L2 (2 MB slice,
//           just written -> guaranteed resident).
// out1 hits DRAM only via writeback; its re-read is an L2 hit.
// Effective DRAM traffic ~384 MB vs 512 MB for plain two-pass.

#define THREADS 256
#define NB 64
#define BPB 32                      // blocks per batch (8192 cols / 256 thr)
#define GRID (NB * BPB)             // 2048

__device__ int g_cnt[NB];

__global__ void reset_counters()
{
    if (threadIdx.x < NB) g_cnt[threadIdx.x] = 0;
}

__device__ __forceinline__ void butterfly64(float v[64])
{
#pragma unroll
    for (int h = 1; h < 64; h <<= 1)
#pragma unroll
        for (int s = 0; s < 64; s += 2 * h)
#pragma unroll
            for (int k = 0; k < h; k++) {
                float a = v[s + k], b = v[s + k + h];
                v[s + k]     = a + b;
                v[s + k + h] = a - b;
            }
}

__global__ __launch_bounds__(THREADS)
void wht2_pipe(const float* __restrict__ x,
               float* __restrict__ out1,
               float* __restrict__ out2)
{
    const int batch = blockIdx.x / BPB;
    const int sub   = blockIdx.x % BPB;
    const unsigned col = (unsigned)sub * THREADS + threadIdx.x;   // 0..8191
    const size_t bbase = (size_t)batch * (64u * 8192u);

    float v[64];

    // ---------------- pass 1: out1[batch] = FWHT_i(x[batch]) ----------------
    {
        // col encodes (j, c): address = bbase + i*8192 + col
        const float* px = x + bbase + col;
#pragma unroll
        for (int k = 0; k < 64; k++)
            v[k] = __ldcs(px + (size_t)k * 8192);     // use-once read of x

        butterfly64(v);

        float* po = out1 + bbase + col;
#pragma unroll
        for (int k = 0; k < 64; k++)
            po[(size_t)k * 8192] = v[k];              // keep in L2 for pass 2
    }

    __threadfence();                                   // release out1 stores
    __syncthreads();
    if (threadIdx.x == 0)
        atomicAdd(&g_cnt[batch], 1);

    // ---------------- wait for 32 sibling blocks of this batch ----------------
    if (threadIdx.x == 0) {
        while (*(volatile int*)&g_cnt[batch] < BPB)
            __nanosleep(32);
    }
    __syncthreads();
    __threadfence();                                   // acquire

    // ---------------- pass 2: out2[batch] = FWHT_j(out1[batch]) ----------------
    {
        // col encodes (i, c): i = col/128, c = col%128
        const size_t base = bbase + (size_t)(col / 128u) * 8192u + (col % 128u);
        const float* pi = out1 + base;
#pragma unroll
        for (int k = 0; k < 64; k++)
            v[k] = __ldcs(pi + (size_t)k * 128);      // L2-hot; evict after use

        butterfly64(v);

        float* po = out2 + base;
#pragma unroll
        for (int k = 0; k < 64; k++)
            __stcs(po + (size_t)k * 128, v[k]);       // use-once write
    }
}

extern "C" void kernel_launch(void* const* d_in, const int* in_sizes, int n_in,
                              void* d_out, int out_size)
{
    const float* x = (const float*)d_in[0];
    float* out1 = (float*)d_out;
    float* out2 = out1 + (size_t)64 * 64 * 64 * 128;

    reset_counters<<<1, 64>>>();
    wht2_pipe<<<GRID, THREADS>>>(x, out1, out2);
}

// round 10
// speedup vs baseline: 1.0259x; 1.0259x over previous
#include <cuda_runtime.h>

// x[64, 64, 64, 128] fp32.
//   out1 = FWHT along axis 1 (i), element stride 8192
//   out2 = FWHT along axis 2 (j) of out1, element stride 128
// d_out = [out1 | out2].
//
// Single pipelined kernel with LAGGED consumption:
//   group b (32 blocks each): pass 1 of batch b, then pass 2 of batch b-K.
//   The consumed batch was produced by groups launched K*32 blocks earlier,
//   so by the time a block finishes its own pass-1 unit the dependency is
//   almost always already satisfied -> near-zero spin (vs sibling-skew wait
//   in the previous version). out1 slices (2 MB/batch, <= K+1 hot at a time)
//   are read back from L2; out1 costs DRAM only its writeback.
//   Effective DRAM traffic ~384 MB vs 512 MB plain two-pass.
//
// Counters self-reset: the 32nd pass-2 block of a batch resets both counters
// (all waiters have passed the spin by then), so state is zero for the next
// graph replay and no prologue kernel is needed.

#define THREADS 256
#define NB 64
#define BPB 32                       // blocks (units) per batch-pass
#define LAG 3
#define GRID ((NB + LAG) * BPB)      // 2144

__device__ int g_cnt1[NB];           // pass-1 completions per batch
__device__ int g_cnt2[NB];           // pass-2 completions per batch

__device__ __forceinline__ void butterfly64(float v[64])
{
#pragma unroll
    for (int h = 1; h < 64; h <<= 1)
#pragma unroll
        for (int s = 0; s < 64; s += 2 * h)
#pragma unroll
            for (int k = 0; k < h; k++) {
                float a = v[s + k], b = v[s + k + h];
                v[s + k]     = a + b;
                v[s + k + h] = a - b;
            }
}

__global__ __launch_bounds__(THREADS)
void wht2_lag(const float* __restrict__ x,
              float* __restrict__ out1,
              float* __restrict__ out2)
{
    const int grp = blockIdx.x / BPB;            // 0 .. NB+LAG-1
    const int sub = blockIdx.x % BPB;
    const unsigned col = (unsigned)sub * THREADS + threadIdx.x;   // 0..8191

    float v[64];

    // ---------------- pass 1: out1[grp] = FWHT_i(x[grp]) ----------------
    if (grp < NB) {
        const size_t bbase = (size_t)grp * (64u * 8192u);
        const float* px = x + bbase + col;       // col = (j,c)
#pragma unroll
        for (int k = 0; k < 64; k++)
            v[k] = __ldcs(px + (size_t)k * 8192);   // use-once read of x

        butterfly64(v);

        float* po = out1 + bbase + col;
#pragma unroll
        for (int k = 0; k < 64; k++)
            po[(size_t)k * 8192] = v[k];            // keep in L2 for pass 2

        __threadfence();                             // release out1 stores
        __syncthreads();
        if (threadIdx.x == 0)
            atomicAdd(&g_cnt1[grp], 1);
    }

    // ---------------- pass 2: out2[m] = FWHT_j(out1[m]), m = grp-LAG ----------------
    if (grp >= LAG) {
        const int m = grp - LAG;

        if (threadIdx.x == 0) {
            while (*(volatile int*)&g_cnt1[m] < BPB)
                __nanosleep(32);
        }
        __syncthreads();
        __threadfence();                             // acquire

        const size_t mbase = (size_t)m * (64u * 8192u);
        const size_t base  = mbase + (size_t)(col / 128u) * 8192u + (col % 128u);
        const float* pi = out1 + base;
#pragma unroll
        for (int k = 0; k < 64; k++)
            v[k] = __ldcs(pi + (size_t)k * 128);    // L2-hot; evict after use

        butterfly64(v);

        float* po = out2 + base;
#pragma unroll
        for (int k = 0; k < 64; k++)
            __stcs(po + (size_t)k * 128, v[k]);     // use-once write

        // self-reset: last finishing pass-2 block clears both counters.
        // All 32 waiters have already passed the spin, so clearing is safe.
        __syncthreads();
        if (threadIdx.x == 0) {
            int done = atomicAdd(&g_cnt2[m], 1) + 1;
            if (done == BPB) {
                atomicExch(&g_cnt2[m], 0);
                atomicExch(&g_cnt1[m], 0);
            }
        }
    }
}

extern "C" void kernel_launch(void* const* d_in, const int* in_sizes, int n_in,
                              void* d_out, int out_size)
{
    const float* x = (const float*)d_in[0];
    float* out1 = (float*)d_out;
    float* out2 = out1 + (size_t)64 * 64 * 64 * 128;

    wht2_lag<<<GRID, THREADS>>>(x, out1, out2);
}